// round 3
// baseline (speedup 1.0000x reference)
#include <cuda_runtime.h>
#include <math.h>

#define T    32
#define Bz   32
#define NIN  512
#define NH   1024
#define NOUT 256
#define NBLK 296      // 2 CTAs/SM * 148 SMs (resident via launch_bounds)
#define NTH  256
#define NGRP 37       // 296 = 37 groups of 8 for the tree barrier

// ---------------- persistent state (device globals; no allocation) ----------
__device__ float dS[T * Bz * NH];       // relu(relu(x)@W_i)      [m=(t,b)][k]
__device__ float dZ[T * Bz * NH];       // relu(S@W_z)            [m][k]
__device__ float dZCt[T * NH * Bz];     // Z@W_c transposed       [t][j][b]
__device__ float dHist[T * NH * Bz];    // h_t per step            [t][j][b]
__device__ float dHcur[NH * Bz];        // carry hs               [j][b]
__device__ float dOt[NH * Bz];          // o = relu(h@W_ho)       [j][b]
__device__ float dPart[8 * NH * Bz];    // split-K partials (8 slices)
__device__ float dDots[T * Bz];         // scaled dot coefficients [tau][b]
// tree barrier state (monotonic counters: zero-init once, never reset)
__device__ unsigned gLeaf[NGRP * 32];   // one counter per 128B line
__device__ unsigned gRoot;
__device__ volatile unsigned gEpoch;

// ---------------- packed f32x2 helpers (FFMA2 only reachable via PTX) -------
static __device__ __forceinline__ unsigned long long pk2(float v) {
    unsigned long long r;
    asm("mov.b64 %0, {%1, %1};" : "=l"(r) : "f"(v));
    return r;
}
static __device__ __forceinline__ void ffma2(unsigned long long& d,
                                             unsigned long long a,
                                             unsigned long long b) {
    asm("fma.rn.f32x2 %0, %1, %2, %0;" : "+l"(d) : "l"(a), "l"(b));
}
static __device__ __forceinline__ float2 up2(unsigned long long v) {
    float2 f;
    asm("mov.b64 {%0, %1}, %2;" : "=f"(f.x), "=f"(f.y) : "l"(v));
    return f;
}

// ---------------- tree-structured software grid barrier ---------------------
// Leaf: 8 CTAs per counter (37 counters, separate L2 lines).
// Root: 37 contenders. Counters are monotonic; modulo arithmetic detects the
// last arrival of each round, so the barrier is CUDA-graph-replay safe.
__device__ __forceinline__ void gsync() {
    __syncthreads();
    if (threadIdx.x == 0) {
        __threadfence();
        unsigned e = gEpoch;
        unsigned grp = (unsigned)blockIdx.x >> 3;
        if ((atomicAdd(&gLeaf[grp << 5], 1u) & 7u) == 7u) {
            if (atomicAdd(&gRoot, 1u) % NGRP == NGRP - 1u) {
                __threadfence();
                atomicAdd((unsigned*)&gEpoch, 1u);
            }
        }
        while (gEpoch == e) {}
        __threadfence();
    }
    __syncthreads();
}

// ---------------- big GEMM device body: C[M,N] = op(A[M,K] @ W[K,N]) --------
// One CTA = one 64x64 tile. BK=16, double-buffered smem, 4x4 f32x2 microtile.
template <bool RIN, bool ROUT, bool TST>
__device__ __forceinline__ void gemm_big_dev(const float* __restrict__ A,
                                             const float* __restrict__ W,
                                             float* __restrict__ C,
                                             int M, int N, int K) {
    __shared__ __align__(16) float As[2][16][64];   // [buf][k][m]
    __shared__ __align__(16) float Bs[2][16][64];   // [buf][k][n]
    int tid = threadIdx.x;
    int tx = tid & 15, ty = tid >> 4;
    int tilesN = N >> 6;
    int m0 = (blockIdx.x / tilesN) << 6;
    int n0 = (blockIdx.x % tilesN) << 6;

    int ra = tid >> 2, ca = (tid & 3) << 2;      // A-load coords
    int rb = tid >> 4, cb = (tid & 15) << 2;     // B-load coords
    const float* Ap = A + (size_t)(m0 + ra) * K + ca;
    const float* Wp = W + (size_t)rb * N + n0 + cb;

    unsigned long long acc[4][2];
#pragma unroll
    for (int i = 0; i < 4; i++) { acc[i][0] = 0ull; acc[i][1] = 0ull; }

    int nch = K >> 4;
    // prologue: chunk 0
    {
        float4 va = *reinterpret_cast<const float4*>(Ap);
        if (RIN) {
            va.x = fmaxf(va.x, 0.f); va.y = fmaxf(va.y, 0.f);
            va.z = fmaxf(va.z, 0.f); va.w = fmaxf(va.w, 0.f);
        }
        float4 vb = *reinterpret_cast<const float4*>(Wp);
        As[0][ca + 0][ra] = va.x; As[0][ca + 1][ra] = va.y;
        As[0][ca + 2][ra] = va.z; As[0][ca + 3][ra] = va.w;
        *reinterpret_cast<float4*>(&Bs[0][rb][cb]) = vb;
    }
    __syncthreads();

    for (int ch = 0; ch < nch; ch++) {
        int cur = ch & 1;
        float4 va, vb;
        if (ch + 1 < nch) {
            va = *reinterpret_cast<const float4*>(Ap + (ch + 1) * 16);
            vb = *reinterpret_cast<const float4*>(Wp + (size_t)(ch + 1) * 16 * N);
            if (RIN) {
                va.x = fmaxf(va.x, 0.f); va.y = fmaxf(va.y, 0.f);
                va.z = fmaxf(va.z, 0.f); va.w = fmaxf(va.w, 0.f);
            }
        }
#pragma unroll
        for (int k = 0; k < 16; k++) {
            float4 a4 = *reinterpret_cast<float4*>(&As[cur][k][ty * 4]);
            ulonglong2 b2 = *reinterpret_cast<ulonglong2*>(&Bs[cur][k][tx * 4]);
            unsigned long long a0 = pk2(a4.x), a1 = pk2(a4.y);
            unsigned long long a2 = pk2(a4.z), a3 = pk2(a4.w);
            ffma2(acc[0][0], a0, b2.x); ffma2(acc[0][1], a0, b2.y);
            ffma2(acc[1][0], a1, b2.x); ffma2(acc[1][1], a1, b2.y);
            ffma2(acc[2][0], a2, b2.x); ffma2(acc[2][1], a2, b2.y);
            ffma2(acc[3][0], a3, b2.x); ffma2(acc[3][1], a3, b2.y);
        }
        if (ch + 1 < nch) {
            int nxt = cur ^ 1;
            As[nxt][ca + 0][ra] = va.x; As[nxt][ca + 1][ra] = va.y;
            As[nxt][ca + 2][ra] = va.z; As[nxt][ca + 3][ra] = va.w;
            *reinterpret_cast<float4*>(&Bs[nxt][rb][cb]) = vb;
        }
        __syncthreads();
    }
#pragma unroll
    for (int i = 0; i < 4; i++) {
        float2 u0 = up2(acc[i][0]);
        float2 u1 = up2(acc[i][1]);
        float vals[4] = {u0.x, u0.y, u1.x, u1.y};
#pragma unroll
        for (int j = 0; j < 4; j++) {
            float v = vals[j];
            if (ROUT) v = fmaxf(v, 0.f);
            int m = m0 + ty * 4 + i;
            int n = n0 + tx * 4 + j;
            if (TST) {
                C[(((size_t)(m >> 5) * NH) + n) * Bz + (m & 31)] = v;  // [t][n][b]
            } else {
                C[(size_t)m * N + n] = v;
            }
        }
    }
}

__global__ void __launch_bounds__(256) k_gemm_s(const float* __restrict__ x,
                                                const float* __restrict__ Wi) {
    gemm_big_dev<true, true, false>(x, Wi, dS, T * Bz, NH, NIN);
}
__global__ void __launch_bounds__(256) k_gemm_z(const float* __restrict__ Wz) {
    gemm_big_dev<false, true, false>(dS, Wz, dZ, T * Bz, NH, NH);
}
__global__ void __launch_bounds__(256) k_gemm_zc(const float* __restrict__ Wc) {
    gemm_big_dev<false, false, true>(dZ, Wc, dZCt, T * Bz, NH, NH);
}

// ---------------- skinny recurrent GEMM (M=32), split-K 8 x 128 -------------
// A layout [k][b]. Tile = 32b x 32j, K-slice 128. Double-buffered smem,
// 2x2 f32x2 microtile.
__device__ void rec_job(const float* __restrict__ At, const float* __restrict__ W,
                        float* __restrict__ part, int N, int jt, int ks) {
    __shared__ __align__(16) float As[2][32][32];   // [buf][k][b]
    __shared__ __align__(16) float Ws[2][32][32];   // [buf][k][j]
    int tid = threadIdx.x;
    int jg = tid & 15;     // j pair
    int bg = tid >> 4;     // b pair
    int j0 = jt << 5;
    int k0 = ks << 7;      // K-slice of 128
    int r = tid >> 3, c = (tid & 7) << 2;
    const float* Ap = At + (size_t)k0 * Bz + 4 * tid;
    const float* Wp = W + (size_t)(k0 + r) * N + j0 + c;

    {
        float4 av = *reinterpret_cast<const float4*>(Ap);
        float4 wv = *reinterpret_cast<const float4*>(Wp);
        *reinterpret_cast<float4*>(&As[0][0][0] + 4 * tid) = av;
        *reinterpret_cast<float4*>(&Ws[0][r][c]) = wv;
    }
    __syncthreads();

    unsigned long long c0 = 0ull, c1 = 0ull;
#pragma unroll
    for (int ch = 0; ch < 4; ch++) {
        int cur = ch & 1;
        float4 av, wv;
        if (ch < 3) {
            av = *reinterpret_cast<const float4*>(Ap + (ch + 1) * 32 * Bz);
            wv = *reinterpret_cast<const float4*>(Wp + (size_t)(ch + 1) * 32 * N);
        }
#pragma unroll
        for (int k = 0; k < 32; k++) {
            float2 a2 = *reinterpret_cast<float2*>(&As[cur][k][bg * 2]);
            unsigned long long wp = *reinterpret_cast<unsigned long long*>(&Ws[cur][k][jg * 2]);
            ffma2(c0, pk2(a2.x), wp);
            ffma2(c1, pk2(a2.y), wp);
        }
        if (ch < 3) {
            int nxt = cur ^ 1;
            *reinterpret_cast<float4*>(&As[nxt][0][0] + 4 * tid) = av;
            *reinterpret_cast<float4*>(&Ws[nxt][r][c]) = wv;
        }
        __syncthreads();
    }
    float* p = part + (size_t)ks * N * Bz;
    float2 u0 = up2(c0), u1 = up2(c1);
    int jj = j0 + jg * 2;
    int b0 = bg * 2;
    p[(size_t)(jj + 0) * Bz + b0 + 0] = u0.x;
    p[(size_t)(jj + 1) * Bz + b0 + 0] = u0.y;
    p[(size_t)(jj + 0) * Bz + b0 + 1] = u1.x;
    p[(size_t)(jj + 1) * Bz + b0 + 1] = u1.y;
}

// ---------------- persistent recurrence kernel ------------------------------
__global__ void __launch_bounds__(NTH, 2)
memnet_rec_kernel(const float* __restrict__ Wh,  const float* __restrict__ Who,
                  const float* __restrict__ Wo,  const float* __restrict__ lam_p,
                  const float* __restrict__ eta_p, const float* __restrict__ g_p,
                  const float* __restrict__ b_p, float* __restrict__ out) {
    int tid  = threadIdx.x;
    int lane = tid & 31;
    int w    = tid >> 5;

    const float lam = lam_p[0];
    const float eta = eta_p[0];

    for (int t = 0; t < T; t++) {
        const float* zc = dZCt + (size_t)t * NH * Bz;
        float* Ht = dHist + (size_t)t * NH * Bz;

        // Phase A: partials of h_prev @ W_h  (h_prev = 0 at t=0 -> skip)
        if (t > 0) {
            for (int job = blockIdx.x; job < 256; job += NBLK)
                rec_job(dHcur, Wh, dPart, NH, job & 31, job >> 5);
            gsync();
        }

        // Phase R: h_new = relu(zc + sum partials) -> Hist[t]
        for (int i = blockIdx.x * NTH + tid; i < NH * Bz; i += NBLK * NTH) {
            float v = zc[i];
            if (t > 0) {
#pragma unroll
                for (int s = 0; s < 8; s++) v += dPart[(size_t)s * NH * Bz + i];
            }
            Ht[i] = fmaxf(v, 0.f);
        }
        gsync();

        // Phase B: partials of h_new @ W_h; plus scaled history dot-products
        {
            int njob = 256 + t + 1;
            for (int job = blockIdx.x; job < njob; job += NBLK) {
                if (job < 256) {
                    rec_job(Ht, Wh, dPart, NH, job & 31, job >> 5);
                } else {
                    int tau = job - 256;
                    const float* Hs = dHist + (size_t)tau * NH * Bz;
                    float a = 0.f;
                    int kbeg = w << 7;
#pragma unroll 8
                    for (int k = kbeg; k < kbeg + 128; k++)
                        a += Ht[(size_t)k * Bz + lane] * Hs[(size_t)k * Bz + lane];
                    __shared__ float red[8][32];
                    __syncthreads();
                    red[w][lane] = a;
                    __syncthreads();
                    if (w == 0) {
                        float s = 0.f;
#pragma unroll
                        for (int i = 0; i < 8; i++) s += red[i][lane];
                        s *= eta * powf(lam, (float)(t - tau));
                        dDots[tau * Bz + lane] = s;
                    }
                    __syncthreads();
                }
            }
        }
        gsync();

        // Phase C: hs = hW + zc + sum_tau d[tau]*H[tau]; batchnorm over b
        {
            int gw = blockIdx.x * 8 + w;   // one warp per hidden unit j
            if (gw < NH) {
                int idx = gw * Bz + lane;
                float acc = zc[idx];
#pragma unroll
                for (int s = 0; s < 8; s++) acc += dPart[(size_t)s * NH * Bz + idx];
#pragma unroll 4
                for (int tau = 0; tau <= t; tau++)
                    acc += dDots[tau * Bz + lane] * dHist[(size_t)tau * NH * Bz + idx];
                float mu = acc;
#pragma unroll
                for (int o = 16; o > 0; o >>= 1) mu += __shfl_xor_sync(0xffffffffu, mu, o);
                mu *= (1.f / 32.f);
                float dv = acc - mu;
                float vv = dv * dv;
#pragma unroll
                for (int o = 16; o > 0; o >>= 1) vv += __shfl_xor_sync(0xffffffffu, vv, o);
                float sig = sqrtf(vv * (1.f / 32.f));
                dHcur[idx] = fmaxf(g_p[gw] * dv / sig + b_p[gw], 0.f);
            }
        }
        gsync();
    }

    // ---- head: o = relu(h @ W_ho) ----
    for (int job = blockIdx.x; job < 256; job += NBLK)
        rec_job(dHcur, Who, dPart, NH, job & 31, job >> 5);
    gsync();
    for (int i = blockIdx.x * NTH + tid; i < NH * Bz; i += NBLK * NTH) {
        float v = 0.f;
#pragma unroll
        for (int s = 0; s < 8; s++) v += dPart[(size_t)s * NH * Bz + i];
        dOt[i] = fmaxf(v, 0.f);
    }
    gsync();

    // ---- y = relu(o @ W_o) ----  N=256: 8 j-tiles * 8 k-slices = 64 jobs
    for (int job = blockIdx.x; job < 64; job += NBLK)
        rec_job(dOt, Wo, dPart, NOUT, job & 7, job >> 3);
    gsync();
    for (int i = blockIdx.x * NTH + tid; i < NOUT * Bz; i += NBLK * NTH) {
        float v = 0.f;
#pragma unroll
        for (int s = 0; s < 8; s++) v += dPart[(size_t)s * NOUT * Bz + i];
        int n = i >> 5, b = i & 31;
        out[(size_t)b * NOUT + n] = fmaxf(v, 0.f);
    }
}

extern "C" void kernel_launch(void* const* d_in, const int* in_sizes, int n_in,
                              void* d_out, int out_size) {
    (void)in_sizes; (void)n_in; (void)out_size;
    const float* x   = (const float*)d_in[0];
    const float* Wi  = (const float*)d_in[1];
    const float* Wz  = (const float*)d_in[2];
    const float* Wc  = (const float*)d_in[3];
    const float* Wh  = (const float*)d_in[4];
    const float* Who = (const float*)d_in[5];
    const float* Wo  = (const float*)d_in[6];
    const float* lam = (const float*)d_in[7];
    const float* eta = (const float*)d_in[8];
    const float* g   = (const float*)d_in[9];
    const float* b   = (const float*)d_in[10];

    k_gemm_s<<<256, 256>>>(x, Wi);
    k_gemm_z<<<256, 256>>>(Wz);
    k_gemm_zc<<<256, 256>>>(Wc);
    memnet_rec_kernel<<<NBLK, NTH>>>(Wh, Who, Wo, lam, eta, g, b, (float*)d_out);
}

// round 4
// speedup vs baseline: 1.1354x; 1.1354x over previous
#include <cuda_runtime.h>
#include <math.h>

#define T    32
#define Bz   32
#define NIN  512
#define NH   1024
#define NOUT 256
#define NBLK 160      // 128 GEMM CTAs (wave 1, distinct SMs) + 32 dot/aux CTAs
#define NTH  256

// ---------------- persistent state (device globals; no allocation) ----------
__device__ float dS[T * Bz * NH];       // relu(relu(x)@W_i)      [m=(t,b)][k]
__device__ float dZ[T * Bz * NH];       // relu(S@W_z)            [m][k]
__device__ float dZCt[T * NH * Bz];     // Z@W_c transposed       [t][j][b]
__device__ float dHist[T * NH * Bz];    // h_t per step            [t][j][b]
__device__ float dHcur[NH * Bz];        // carry hs               [j][b]
__device__ float dOt[NH * Bz];          // o = relu(h@W_ho)       [j][b]
__device__ float dPart[8 * NH * Bz];    // split-K partials (8 slices)
__device__ float dDots[T * Bz];         // scaled dot coefficients [tau][b]
__device__ unsigned gArrive;            // zero-initialized
__device__ volatile unsigned gEpoch;    // monotonic across replays

// ---------------- packed f32x2 helpers --------------------------------------
static __device__ __forceinline__ unsigned long long pk2(float v) {
    unsigned long long r;
    asm("mov.b64 %0, {%1, %1};" : "=l"(r) : "f"(v));
    return r;
}
static __device__ __forceinline__ void ffma2(unsigned long long& d,
                                             unsigned long long a,
                                             unsigned long long b) {
    asm("fma.rn.f32x2 %0, %1, %2, %0;" : "+l"(d) : "l"(a), "l"(b));
}
static __device__ __forceinline__ float2 up2(unsigned long long v) {
    float2 f;
    asm("mov.b64 {%0, %1}, %2;" : "=f"(f.x), "=f"(f.y) : "l"(v));
    return f;
}

// ---------------- flat software grid barrier (R2 version; measured best) ----
__device__ __forceinline__ void gsync() {
    __syncthreads();
    if (threadIdx.x == 0) {
        __threadfence();
        unsigned e = gEpoch;
        if (atomicAdd(&gArrive, 1u) == NBLK - 1u) {
            gArrive = 0u;
            __threadfence();
            atomicAdd((unsigned*)&gEpoch, 1u);
        } else {
            while (gEpoch == e) { __nanosleep(16); }
        }
        __threadfence();
    }
    __syncthreads();
}

// ---------------- big GEMM (precompute): C[M,N] = op(A[M,K] @ W[K,N]) -------
template <bool RIN, bool ROUT, bool TST>
__device__ __forceinline__ void gemm_big_dev(const float* __restrict__ A,
                                             const float* __restrict__ W,
                                             float* __restrict__ C,
                                             int M, int N, int K) {
    __shared__ __align__(16) float As[2][16][64];
    __shared__ __align__(16) float Bs[2][16][64];
    int tid = threadIdx.x;
    int tx = tid & 15, ty = tid >> 4;
    int tilesN = N >> 6;
    int m0 = (blockIdx.x / tilesN) << 6;
    int n0 = (blockIdx.x % tilesN) << 6;

    int ra = tid >> 2, ca = (tid & 3) << 2;
    int rb = tid >> 4, cb = (tid & 15) << 2;
    const float* Ap = A + (size_t)(m0 + ra) * K + ca;
    const float* Wp = W + (size_t)rb * N + n0 + cb;

    unsigned long long acc[4][2];
#pragma unroll
    for (int i = 0; i < 4; i++) { acc[i][0] = 0ull; acc[i][1] = 0ull; }

    int nch = K >> 4;
    {
        float4 va = *reinterpret_cast<const float4*>(Ap);
        if (RIN) {
            va.x = fmaxf(va.x, 0.f); va.y = fmaxf(va.y, 0.f);
            va.z = fmaxf(va.z, 0.f); va.w = fmaxf(va.w, 0.f);
        }
        float4 vb = *reinterpret_cast<const float4*>(Wp);
        As[0][ca + 0][ra] = va.x; As[0][ca + 1][ra] = va.y;
        As[0][ca + 2][ra] = va.z; As[0][ca + 3][ra] = va.w;
        *reinterpret_cast<float4*>(&Bs[0][rb][cb]) = vb;
    }
    __syncthreads();

    for (int ch = 0; ch < nch; ch++) {
        int cur = ch & 1;
        float4 va, vb;
        if (ch + 1 < nch) {
            va = *reinterpret_cast<const float4*>(Ap + (ch + 1) * 16);
            vb = *reinterpret_cast<const float4*>(Wp + (size_t)(ch + 1) * 16 * N);
            if (RIN) {
                va.x = fmaxf(va.x, 0.f); va.y = fmaxf(va.y, 0.f);
                va.z = fmaxf(va.z, 0.f); va.w = fmaxf(va.w, 0.f);
            }
        }
#pragma unroll
        for (int k = 0; k < 16; k++) {
            float4 a4 = *reinterpret_cast<float4*>(&As[cur][k][ty * 4]);
            ulonglong2 b2 = *reinterpret_cast<ulonglong2*>(&Bs[cur][k][tx * 4]);
            unsigned long long a0 = pk2(a4.x), a1 = pk2(a4.y);
            unsigned long long a2 = pk2(a4.z), a3 = pk2(a4.w);
            ffma2(acc[0][0], a0, b2.x); ffma2(acc[0][1], a0, b2.y);
            ffma2(acc[1][0], a1, b2.x); ffma2(acc[1][1], a1, b2.y);
            ffma2(acc[2][0], a2, b2.x); ffma2(acc[2][1], a2, b2.y);
            ffma2(acc[3][0], a3, b2.x); ffma2(acc[3][1], a3, b2.y);
        }
        if (ch + 1 < nch) {
            int nxt = cur ^ 1;
            As[nxt][ca + 0][ra] = va.x; As[nxt][ca + 1][ra] = va.y;
            As[nxt][ca + 2][ra] = va.z; As[nxt][ca + 3][ra] = va.w;
            *reinterpret_cast<float4*>(&Bs[nxt][rb][cb]) = vb;
        }
        __syncthreads();
    }
#pragma unroll
    for (int i = 0; i < 4; i++) {
        float2 u0 = up2(acc[i][0]);
        float2 u1 = up2(acc[i][1]);
        float vals[4] = {u0.x, u0.y, u1.x, u1.y};
#pragma unroll
        for (int j = 0; j < 4; j++) {
            float v = vals[j];
            if (ROUT) v = fmaxf(v, 0.f);
            int m = m0 + ty * 4 + i;
            int n = n0 + tx * 4 + j;
            if (TST) {
                C[(((size_t)(m >> 5) * NH) + n) * Bz + (m & 31)] = v;  // [t][n][b]
            } else {
                C[(size_t)m * N + n] = v;
            }
        }
    }
}

__global__ void __launch_bounds__(256) k_gemm_s(const float* __restrict__ x,
                                                const float* __restrict__ Wi) {
    gemm_big_dev<true, true, false>(x, Wi, dS, T * Bz, NH, NIN);
}
__global__ void __launch_bounds__(256) k_gemm_z(const float* __restrict__ Wz) {
    gemm_big_dev<false, true, false>(dS, Wz, dZ, T * Bz, NH, NH);
}
__global__ void __launch_bounds__(256) k_gemm_zc(const float* __restrict__ Wc) {
    gemm_big_dev<false, false, true>(dZ, Wc, dZCt, T * Bz, NH, NH);
}

// ---------------- persistent recurrence kernel ------------------------------
// GEMM job (CTA bx<128): jt = bx&15 -> j0 = jt*64 ; ks = bx>>4 -> k0 = ks*128.
// W slice [128k][64j] resident in smem for the whole kernel.
// Thread tile: 2b x 4j (bg = tid>>4, jg = tid&15), packed f32x2, 4 acc chains.
struct SmemT {
    float Ws[128][64];   // 32 KB resident weight slice
    float As[64][32];    // 8 KB A chunk ([k][b])
    float red[8][32];
};

__device__ __forceinline__ void load_wslice(SmemT* sm, const float* __restrict__ W,
                                            int k0, int j0, int ldw) {
    int tid = threadIdx.x;
    for (int i = tid * 4; i < 128 * 64; i += NTH * 4) {
        int r = i >> 6, c = i & 63;
        *reinterpret_cast<float4*>(&sm->Ws[r][c]) =
            *reinterpret_cast<const float4*>(W + (size_t)(k0 + r) * ldw + j0 + c);
    }
}

__device__ __forceinline__ void resident_gemm(SmemT* sm, const float* __restrict__ At,
                                              float* __restrict__ pslice,
                                              int k0, int j0) {
    int tid = threadIdx.x;
    int bg = tid >> 4, jg = tid & 15;
    unsigned long long a0 = 0ull, a1 = 0ull, a2 = 0ull, a3 = 0ull;
#pragma unroll
    for (int c = 0; c < 2; c++) {
        const float4* src = reinterpret_cast<const float4*>(At + (size_t)(k0 + c * 64) * Bz);
        float4 v0 = src[tid * 2];
        float4 v1 = src[tid * 2 + 1];
        reinterpret_cast<float4*>(&sm->As[0][0])[tid * 2] = v0;
        reinterpret_cast<float4*>(&sm->As[0][0])[tid * 2 + 1] = v1;
        __syncthreads();
#pragma unroll
        for (int k = 0; k < 64; k++) {
            float2 a = *reinterpret_cast<float2*>(&sm->As[k][bg * 2]);
            ulonglong2 wq = *reinterpret_cast<ulonglong2*>(&sm->Ws[c * 64 + k][jg * 4]);
            unsigned long long ax = pk2(a.x), ay = pk2(a.y);
            ffma2(a0, ax, wq.x); ffma2(a1, ax, wq.y);
            ffma2(a2, ay, wq.x); ffma2(a3, ay, wq.y);
        }
        __syncthreads();
    }
    float2 u0 = up2(a0), u1 = up2(a1), u2 = up2(a2), u3 = up2(a3);
    int jj = j0 + jg * 4, b0 = bg * 2;
    float2 s0 = {u0.x, u2.x};
    float2 s1 = {u0.y, u2.y};
    float2 s2 = {u1.x, u3.x};
    float2 s3 = {u1.y, u3.y};
    *reinterpret_cast<float2*>(&pslice[(size_t)(jj + 0) * Bz + b0]) = s0;
    *reinterpret_cast<float2*>(&pslice[(size_t)(jj + 1) * Bz + b0]) = s1;
    *reinterpret_cast<float2*>(&pslice[(size_t)(jj + 2) * Bz + b0]) = s2;
    *reinterpret_cast<float2*>(&pslice[(size_t)(jj + 3) * Bz + b0]) = s3;
}

__global__ void __launch_bounds__(NTH, 2)
memnet_rec_kernel(const float* __restrict__ Wh,  const float* __restrict__ Who,
                  const float* __restrict__ Wo,  const float* __restrict__ lam_p,
                  const float* __restrict__ eta_p, const float* __restrict__ g_p,
                  const float* __restrict__ b_p, float* __restrict__ out) {
    __shared__ SmemT sm;
    int bx   = blockIdx.x;
    int tid  = threadIdx.x;
    int lane = tid & 31;
    int w    = tid >> 5;
    bool isG = bx < 128;
    int jt = bx & 15, ks = bx >> 4;
    int j0 = jt << 6, k0 = ks << 7;

    if (isG) load_wslice(&sm, Wh, k0, j0, NH);
    __syncthreads();

    const float lam = lam_p[0];
    const float eta = eta_p[0];

    for (int t = 0; t < T; t++) {
        const float* zc = dZCt + (size_t)t * NH * Bz;
        float* Ht = dHist + (size_t)t * NH * Bz;

        // Phase A: partials of h_prev @ W_h  (h_prev = 0 at t=0 -> skip)
        if (t > 0) {
            if (isG) resident_gemm(&sm, dHcur, dPart + (size_t)ks * NH * Bz, k0, j0);
            gsync();
        }

        // Phase R: h_new = relu(zc + sum partials) -> Hist[t]
        for (int i = (bx * NTH + tid) * 4; i < NH * Bz; i += NBLK * NTH * 4) {
            float4 v = *reinterpret_cast<const float4*>(zc + i);
            if (t > 0) {
#pragma unroll
                for (int s = 0; s < 8; s++) {
                    float4 p = *reinterpret_cast<const float4*>(dPart + (size_t)s * NH * Bz + i);
                    v.x += p.x; v.y += p.y; v.z += p.z; v.w += p.w;
                }
            }
            v.x = fmaxf(v.x, 0.f); v.y = fmaxf(v.y, 0.f);
            v.z = fmaxf(v.z, 0.f); v.w = fmaxf(v.w, 0.f);
            *reinterpret_cast<float4*>(Ht + i) = v;
        }
        gsync();

        // Phase B: GEMM partials of h_new @ W_h (CTAs 0..127); dots (CTAs 128..128+t)
        if (isG) {
            resident_gemm(&sm, Ht, dPart + (size_t)ks * NH * Bz, k0, j0);
        } else if (bx - 128 <= t) {
            int tau = bx - 128;
            const float* Hs = dHist + (size_t)tau * NH * Bz;
            float a = 0.f;
            int kbeg = w << 7;
#pragma unroll 8
            for (int k = kbeg; k < kbeg + 128; k++)
                a += Ht[(size_t)k * Bz + lane] * Hs[(size_t)k * Bz + lane];
            __syncthreads();
            sm.red[w][lane] = a;
            __syncthreads();
            if (w == 0) {
                float s = 0.f;
#pragma unroll
                for (int i = 0; i < 8; i++) s += sm.red[i][lane];
                s *= eta * powf(lam, (float)(t - tau));
                dDots[tau * Bz + lane] = s;
            }
        }
        gsync();

        // Phase C: hs = hW + zc + sum_tau d[tau]*H[tau]; batchnorm over b
        {
            int gw = bx * 8 + w;   // one warp per hidden unit j (CTAs 0..127)
            if (gw < NH) {
                int idx = gw * Bz + lane;
                float acc = zc[idx];
#pragma unroll
                for (int s = 0; s < 8; s++) acc += dPart[(size_t)s * NH * Bz + idx];
#pragma unroll 4
                for (int tau = 0; tau <= t; tau++)
                    acc += dDots[tau * Bz + lane] * dHist[(size_t)tau * NH * Bz + idx];
                float mu = acc;
#pragma unroll
                for (int o = 16; o > 0; o >>= 1) mu += __shfl_xor_sync(0xffffffffu, mu, o);
                mu *= (1.f / 32.f);
                float dv = acc - mu;
                float vv = dv * dv;
#pragma unroll
                for (int o = 16; o > 0; o >>= 1) vv += __shfl_xor_sync(0xffffffffu, vv, o);
                float sig = sqrtf(vv * (1.f / 32.f));
                dHcur[idx] = fmaxf(g_p[gw] * dv / sig + b_p[gw], 0.f);
            }
        }
        gsync();
    }

    // ---- head: o = relu(h @ W_ho) ----
    if (isG) {
        load_wslice(&sm, Who, k0, j0, NH);
        __syncthreads();
        resident_gemm(&sm, dHcur, dPart + (size_t)ks * NH * Bz, k0, j0);
    }
    gsync();
    for (int i = (bx * NTH + tid) * 4; i < NH * Bz; i += NBLK * NTH * 4) {
        float4 v = *reinterpret_cast<const float4*>(dPart + i);
#pragma unroll
        for (int s = 1; s < 8; s++) {
            float4 p = *reinterpret_cast<const float4*>(dPart + (size_t)s * NH * Bz + i);
            v.x += p.x; v.y += p.y; v.z += p.z; v.w += p.w;
        }
        v.x = fmaxf(v.x, 0.f); v.y = fmaxf(v.y, 0.f);
        v.z = fmaxf(v.z, 0.f); v.w = fmaxf(v.w, 0.f);
        *reinterpret_cast<float4*>(dOt + i) = v;
    }
    gsync();

    // ---- y = relu(o @ W_o) ----  N=256: 4 jt * 8 ks = 32 jobs
    if (bx < 32) {
        int jt2 = bx & 3, ks2 = bx >> 2;
        int j02 = jt2 << 6, k02 = ks2 << 7;
        load_wslice(&sm, Wo, k02, j02, NOUT);
        __syncthreads();
        resident_gemm(&sm, dOt, dPart + (size_t)ks2 * NOUT * Bz, k02, j02);
    }
    gsync();
    for (int i = bx * NTH + tid; i < NOUT * Bz; i += NBLK * NTH) {
        float v = 0.f;
#pragma unroll
        for (int s = 0; s < 8; s++) v += dPart[(size_t)s * NOUT * Bz + i];
        int n = i >> 5, b = i & 31;
        out[(size_t)b * NOUT + n] = fmaxf(v, 0.f);
    }
}

extern "C" void kernel_launch(void* const* d_in, const int* in_sizes, int n_in,
                              void* d_out, int out_size) {
    (void)in_sizes; (void)n_in; (void)out_size;
    const float* x   = (const float*)d_in[0];
    const float* Wi  = (const float*)d_in[1];
    const float* Wz  = (const float*)d_in[2];
    const float* Wc  = (const float*)d_in[3];
    const float* Wh  = (const float*)d_in[4];
    const float* Who = (const float*)d_in[5];
    const float* Wo  = (const float*)d_in[6];
    const float* lam = (const float*)d_in[7];
    const float* eta = (const float*)d_in[8];
    const float* g   = (const float*)d_in[9];
    const float* b   = (const float*)d_in[10];

    k_gemm_s<<<256, 256>>>(x, Wi);
    k_gemm_z<<<256, 256>>>(Wz);
    k_gemm_zc<<<256, 256>>>(Wc);
    memnet_rec_kernel<<<NBLK, NTH>>>(Wh, Who, Wo, lam, eta, g, b, (float*)d_out);
}

// round 7
// speedup vs baseline: 1.1855x; 1.0441x over previous
#include <cuda_runtime.h>
#include <math.h>

#define T    32
#define Bz   32
#define NIN  512
#define NH   1024
#define NOUT 256
#define NBLK 128      // uniform grid: 8 k-slices x 16 j-tiles
#define NTH  256

// ---------------- persistent state (device globals; no allocation) ----------
__device__ float dS[T * Bz * NH];       // relu(relu(x)@W_i)      [m=(t,b)][k]
__device__ float dZ[T * Bz * NH];       // relu(S@W_z)            [m][k]
__device__ float dZCt[T * NH * Bz];     // Z@W_c transposed       [t][j][b]
__device__ float dHist[T * NH * Bz];    // h_t history             [t][j][b]
__device__ float dHcur[NH * Bz];        // carry hs               [j][b]
__device__ float dOt[NH * Bz];          // o = relu(h@W_ho)       [j][b]
__device__ float dPartA[8 * NH * Bz];   // split-K partials (phase A / head)
__device__ float dPartB[8 * NH * Bz];   // split-K partials (phase B)
__device__ float dDotsRaw[T * Bz];      // raw dot accumulators [tau][b]
// tree barrier (monotonic counters; zero-init once; graph-replay safe)
__device__ unsigned gLeaf[16 * 32];     // 16 counters, one per 128B line
__device__ unsigned gRoot;
__device__ volatile unsigned gEpoch;

// ---------------- packed f32x2 helpers --------------------------------------
static __device__ __forceinline__ unsigned long long pk2(float v) {
    unsigned long long r;
    asm("mov.b64 %0, {%1, %1};" : "=l"(r) : "f"(v));
    return r;
}
static __device__ __forceinline__ void ffma2(unsigned long long& d,
                                             unsigned long long a,
                                             unsigned long long b) {
    asm("fma.rn.f32x2 %0, %1, %2, %0;" : "+l"(d) : "l"(a), "l"(b));
}
static __device__ __forceinline__ float2 up2(unsigned long long v) {
    float2 f;
    asm("mov.b64 {%0, %1}, %2;" : "=f"(f.x), "=f"(f.y) : "l"(v));
    return f;
}

// ---------------- tree grid barrier (128 CTAs: 16 groups of 8) --------------
__device__ __forceinline__ void gsync() {
    __syncthreads();
    if (threadIdx.x == 0) {
        __threadfence();
        unsigned e = gEpoch;
        if ((atomicAdd(&gLeaf[((unsigned)blockIdx.x >> 3) << 5], 1u) & 7u) == 7u) {
            if ((atomicAdd(&gRoot, 1u) & 15u) == 15u) {
                __threadfence();
                atomicAdd((unsigned*)&gEpoch, 1u);
            }
        }
        while (gEpoch == e) {}
        __threadfence();
    }
    __syncthreads();
}

// ---------------- big GEMM (precompute): C[M,N] = op(A[M,K] @ W[K,N]) -------
template <bool RIN, bool ROUT, bool TST>
__device__ __forceinline__ void gemm_big_dev(const float* __restrict__ A,
                                             const float* __restrict__ W,
                                             float* __restrict__ C,
                                             int M, int N, int K) {
    __shared__ __align__(16) float As[2][16][64];
    __shared__ __align__(16) float Bs[2][16][64];
    int tid = threadIdx.x;
    int tx = tid & 15, ty = tid >> 4;
    int tilesN = N >> 6;
    int m0 = (blockIdx.x / tilesN) << 6;
    int n0 = (blockIdx.x % tilesN) << 6;

    int ra = tid >> 2, ca = (tid & 3) << 2;
    int rb = tid >> 4, cb = (tid & 15) << 2;
    const float* Ap = A + (size_t)(m0 + ra) * K + ca;
    const float* Wp = W + (size_t)rb * N + n0 + cb;

    unsigned long long acc[4][2];
#pragma unroll
    for (int i = 0; i < 4; i++) { acc[i][0] = 0ull; acc[i][1] = 0ull; }

    int nch = K >> 4;
    {
        float4 va = *reinterpret_cast<const float4*>(Ap);
        if (RIN) {
            va.x = fmaxf(va.x, 0.f); va.y = fmaxf(va.y, 0.f);
            va.z = fmaxf(va.z, 0.f); va.w = fmaxf(va.w, 0.f);
        }
        float4 vb = *reinterpret_cast<const float4*>(Wp);
        As[0][ca + 0][ra] = va.x; As[0][ca + 1][ra] = va.y;
        As[0][ca + 2][ra] = va.z; As[0][ca + 3][ra] = va.w;
        *reinterpret_cast<float4*>(&Bs[0][rb][cb]) = vb;
    }
    __syncthreads();

    for (int ch = 0; ch < nch; ch++) {
        int cur = ch & 1;
        float4 va, vb;
        if (ch + 1 < nch) {
            va = *reinterpret_cast<const float4*>(Ap + (ch + 1) * 16);
            vb = *reinterpret_cast<const float4*>(Wp + (size_t)(ch + 1) * 16 * N);
            if (RIN) {
                va.x = fmaxf(va.x, 0.f); va.y = fmaxf(va.y, 0.f);
                va.z = fmaxf(va.z, 0.f); va.w = fmaxf(va.w, 0.f);
            }
        }
#pragma unroll
        for (int k = 0; k < 16; k++) {
            float4 a4 = *reinterpret_cast<float4*>(&As[cur][k][ty * 4]);
            ulonglong2 b2 = *reinterpret_cast<ulonglong2*>(&Bs[cur][k][tx * 4]);
            unsigned long long a0 = pk2(a4.x), a1 = pk2(a4.y);
            unsigned long long a2 = pk2(a4.z), a3 = pk2(a4.w);
            ffma2(acc[0][0], a0, b2.x); ffma2(acc[0][1], a0, b2.y);
            ffma2(acc[1][0], a1, b2.x); ffma2(acc[1][1], a1, b2.y);
            ffma2(acc[2][0], a2, b2.x); ffma2(acc[2][1], a2, b2.y);
            ffma2(acc[3][0], a3, b2.x); ffma2(acc[3][1], a3, b2.y);
        }
        if (ch + 1 < nch) {
            int nxt = cur ^ 1;
            As[nxt][ca + 0][ra] = va.x; As[nxt][ca + 1][ra] = va.y;
            As[nxt][ca + 2][ra] = va.z; As[nxt][ca + 3][ra] = va.w;
            *reinterpret_cast<float4*>(&Bs[nxt][rb][cb]) = vb;
        }
        __syncthreads();
    }
#pragma unroll
    for (int i = 0; i < 4; i++) {
        float2 u0 = up2(acc[i][0]);
        float2 u1 = up2(acc[i][1]);
        float vals[4] = {u0.x, u0.y, u1.x, u1.y};
#pragma unroll
        for (int j = 0; j < 4; j++) {
            float v = vals[j];
            if (ROUT) v = fmaxf(v, 0.f);
            int m = m0 + ty * 4 + i;
            int n = n0 + tx * 4 + j;
            if (TST) {
                C[(((size_t)(m >> 5) * NH) + n) * Bz + (m & 31)] = v;  // [t][n][b]
            } else {
                C[(size_t)m * N + n] = v;
            }
        }
    }
}

__global__ void __launch_bounds__(256) k_gemm_s(const float* __restrict__ x,
                                                const float* __restrict__ Wi) {
    gemm_big_dev<true, true, false>(x, Wi, dS, T * Bz, NH, NIN);
}
__global__ void __launch_bounds__(256) k_gemm_z(const float* __restrict__ Wz) {
    gemm_big_dev<false, true, false>(dS, Wz, dZ, T * Bz, NH, NH);
}
__global__ void __launch_bounds__(256) k_gemm_zc(const float* __restrict__ Wc) {
    gemm_big_dev<false, false, true>(dZ, Wc, dZCt, T * Bz, NH, NH);
}

// ---------------- persistent recurrence kernel ------------------------------
// CTA bx: jt = bx&15 (j0 = jt*64), ks = bx>>4 (k0 = ks*128).
// smem: resident 128x64 W slice + staged 128x32 A slice. Exactly 48 KB.
struct SmemT {
    float Ws[128][64];   // 32 KB
    float As[128][32];   // 16 KB
};

__device__ __forceinline__ void load_wslice(SmemT* sm, const float* __restrict__ W,
                                            int k0, int j0, int ldw) {
    int tid = threadIdx.x;
#pragma unroll
    for (int i = 0; i < 8; i++) {
        int e = (tid + i * NTH) * 4;
        int r = e >> 6, c = e & 63;
        *reinterpret_cast<float4*>(&sm->Ws[r][c]) =
            *reinterpret_cast<const float4*>(W + (size_t)(k0 + r) * ldw + j0 + c);
    }
}

// stage a [128][32] slice (contiguous 4096 floats) from global into smem As
__device__ __forceinline__ void load_aslice(SmemT* sm, const float* __restrict__ src) {
    int tid = threadIdx.x;
    float4* d = reinterpret_cast<float4*>(&sm->As[0][0]);
    const float4* s = reinterpret_cast<const float4*>(src);
#pragma unroll
    for (int i = 0; i < 4; i++) d[tid + i * NTH] = s[tid + i * NTH];
}

// GEMM over resident smem tiles: pslice[j][b] for j in [j0, j0+64)
__device__ __forceinline__ void slice_gemm(SmemT* sm, float* __restrict__ pslice,
                                           int j0) {
    int tid = threadIdx.x;
    int bg = tid >> 4, jg = tid & 15;
    unsigned long long c0 = 0ull, c1 = 0ull, c2 = 0ull, c3 = 0ull;
    for (int ko = 0; ko < 128; ko += 16) {
#pragma unroll
        for (int ku = 0; ku < 16; ku++) {
            int k = ko + ku;
            float2 a = *reinterpret_cast<const float2*>(&sm->As[k][bg * 2]);
            ulonglong2 wq = *reinterpret_cast<const ulonglong2*>(&sm->Ws[k][jg * 4]);
            unsigned long long ax = pk2(a.x), ay = pk2(a.y);
            ffma2(c0, ax, wq.x); ffma2(c1, ax, wq.y);
            ffma2(c2, ay, wq.x); ffma2(c3, ay, wq.y);
        }
    }
    float2 u0 = up2(c0), u1 = up2(c1), u2 = up2(c2), u3 = up2(c3);
    int jj = j0 + jg * 4, b0 = bg * 2;
    float2 s0 = {u0.x, u2.x};
    float2 s1 = {u0.y, u2.y};
    float2 s2 = {u1.x, u3.x};
    float2 s3 = {u1.y, u3.y};
    *reinterpret_cast<float2*>(&pslice[(size_t)(jj + 0) * Bz + b0]) = s0;
    *reinterpret_cast<float2*>(&pslice[(size_t)(jj + 1) * Bz + b0]) = s1;
    *reinterpret_cast<float2*>(&pslice[(size_t)(jj + 2) * Bz + b0]) = s2;
    *reinterpret_cast<float2*>(&pslice[(size_t)(jj + 3) * Bz + b0]) = s3;
}

__global__ void __launch_bounds__(NTH, 1)
memnet_rec_kernel(const float* __restrict__ Wh,  const float* __restrict__ Who,
                  const float* __restrict__ Wo,  const float* __restrict__ lam_p,
                  const float* __restrict__ eta_p, const float* __restrict__ g_p,
                  const float* __restrict__ b_p, float* __restrict__ out) {
    __shared__ SmemT sm;
    int bx   = blockIdx.x;
    int tid  = threadIdx.x;
    int lane = tid & 31;
    int w    = tid >> 5;
    int jt = bx & 15, ks = bx >> 4;
    int j0 = jt << 6, k0 = ks << 7;

    load_wslice(&sm, Wh, k0, j0, NH);
    if (bx == 0) {                      // zero dot accumulators for t=0
        float4 z = {0.f, 0.f, 0.f, 0.f};
        reinterpret_cast<float4*>(dDotsRaw)[tid] = z;
    }
    gsync();

    const float lam = lam_p[0];
    const float eta = eta_p[0];

    for (int t = 0; t < T; t++) {
        const float* zc = dZCt + (size_t)t * NH * Bz;
        float* Ht = dHist + (size_t)t * NH * Bz;

        // ---- Phase A: partials of h_prev @ W_h; zero dDotsRaw (t>0) --------
        if (t > 0) {
            load_aslice(&sm, dHcur + (size_t)k0 * Bz);
            __syncthreads();
            slice_gemm(&sm, dPartA + (size_t)ks * NH * Bz, j0);
            if (bx == 0) {
                float4 z = {0.f, 0.f, 0.f, 0.f};
                reinterpret_cast<float4*>(dDotsRaw)[tid] = z;
            }
            gsync();
        }

        // ---- Phase B: build Ht slice in smem; dots; GEMM Ht @ W_h ----------
        {
            // build Ht slice = relu(zc + sum partials) into As (+ global by jt==0)
            float4* d = reinterpret_cast<float4*>(&sm.As[0][0]);
            const float4* zc4 = reinterpret_cast<const float4*>(zc + (size_t)k0 * Bz);
#pragma unroll
            for (int i = 0; i < 4; i++) {
                int idx = tid + i * NTH;
                float4 v = zc4[idx];
                if (t > 0) {
#pragma unroll
                    for (int s = 0; s < 8; s++) {
                        float4 p = reinterpret_cast<const float4*>(
                            dPartA + (size_t)s * NH * Bz + (size_t)k0 * Bz)[idx];
                        v.x += p.x; v.y += p.y; v.z += p.z; v.w += p.w;
                    }
                }
                v.x = fmaxf(v.x, 0.f); v.y = fmaxf(v.y, 0.f);
                v.z = fmaxf(v.z, 0.f); v.w = fmaxf(v.w, 0.f);
                d[idx] = v;
                if (jt == 0)
                    reinterpret_cast<float4*>(Ht + (size_t)k0 * Bz)[idx] = v;
            }
            __syncthreads();

            // dots: this CTA handles tau = jt, jt+16 (<= t) over its k-slice
            for (int tau = jt; tau <= t; tau += 16) {
                float a = 0.f;
                int kb = w << 4;
                if (tau == t) {
#pragma unroll
                    for (int kk = 0; kk < 16; kk++) {
                        float xv = sm.As[kb + kk][lane];
                        a += xv * xv;
                    }
                } else {
                    const float* Hs = dHist + (size_t)tau * NH * Bz + (size_t)k0 * Bz;
#pragma unroll
                    for (int kk = 0; kk < 16; kk++)
                        a += sm.As[kb + kk][lane] * Hs[(kb + kk) * Bz + lane];
                }
                atomicAdd(&dDotsRaw[tau * Bz + lane], a);   // RED (no return)
            }

            slice_gemm(&sm, dPartB + (size_t)ks * NH * Bz, j0);
        }
        gsync();

        // ---- Phase C: hs = HtWh + zc + mem-term; batchnorm over b ----------
        {
            int gw = bx * 8 + w;            // one warp per hidden unit j
            int idx = gw * Bz + lane;
            float acc = zc[idx];
#pragma unroll
            for (int s = 0; s < 8; s++) acc += dPartB[(size_t)s * NH * Bz + idx];
            float sc = eta;
#pragma unroll 4
            for (int tau = t; tau >= 0; tau--) {
                acc += sc * dDotsRaw[tau * Bz + lane]
                          * dHist[(size_t)tau * NH * Bz + idx];
                sc *= lam;
            }
            float mu = acc;
#pragma unroll
            for (int o = 16; o > 0; o >>= 1) mu += __shfl_xor_sync(0xffffffffu, mu, o);
            mu *= (1.f / 32.f);
            float dv = acc - mu;
            float vv = dv * dv;
#pragma unroll
            for (int o = 16; o > 0; o >>= 1) vv += __shfl_xor_sync(0xffffffffu, vv, o);
            float sig = sqrtf(vv * (1.f / 32.f));
            dHcur[idx] = fmaxf(g_p[gw] * dv / sig + b_p[gw], 0.f);
        }
        gsync();
    }

    // ---- head: o = relu(h @ W_ho) ----
    load_wslice(&sm, Who, k0, j0, NH);
    load_aslice(&sm, dHcur + (size_t)k0 * Bz);
    __syncthreads();
    slice_gemm(&sm, dPartA + (size_t)ks * NH * Bz, j0);
    gsync();
    for (int i = (bx * NTH + tid) * 4; i < NH * Bz; i += NBLK * NTH * 4) {
        float4 v = *reinterpret_cast<const float4*>(dPartA + i);
#pragma unroll
        for (int s = 1; s < 8; s++) {
            float4 p = *reinterpret_cast<const float4*>(dPartA + (size_t)s * NH * Bz + i);
            v.x += p.x; v.y += p.y; v.z += p.z; v.w += p.w;
        }
        v.x = fmaxf(v.x, 0.f); v.y = fmaxf(v.y, 0.f);
        v.z = fmaxf(v.z, 0.f); v.w = fmaxf(v.w, 0.f);
        *reinterpret_cast<float4*>(dOt + i) = v;
    }
    gsync();

    // ---- y = relu(o @ W_o) ----  32 jobs: 4 jt x 8 ks
    if (bx < 32) {
        int jt2 = bx & 3, ks2 = bx >> 2;
        int j02 = jt2 << 6, k02 = ks2 << 7;
        load_wslice(&sm, Wo, k02, j02, NOUT);
        load_aslice(&sm, dOt + (size_t)k02 * Bz);
        __syncthreads();
        slice_gemm(&sm, dPartA + (size_t)ks2 * NOUT * Bz, j02);
    }
    gsync();
    for (int i = bx * NTH + tid; i < NOUT * Bz; i += NBLK * NTH) {
        float v = 0.f;
#pragma unroll
        for (int s = 0; s < 8; s++) v += dPartA[(size_t)s * NOUT * Bz + i];
        int n = i >> 5, b = i & 31;
        out[(size_t)b * NOUT + n] = fmaxf(v, 0.f);
    }
}

extern "C" void kernel_launch(void* const* d_in, const int* in_sizes, int n_in,
                              void* d_out, int out_size) {
    (void)in_sizes; (void)n_in; (void)out_size;
    const float* x   = (const float*)d_in[0];
    const float* Wi  = (const float*)d_in[1];
    const float* Wz  = (const float*)d_in[2];
    const float* Wc  = (const float*)d_in[3];
    const float* Wh  = (const float*)d_in[4];
    const float* Who = (const float*)d_in[5];
    const float* Wo  = (const float*)d_in[6];
    const float* lam = (const float*)d_in[7];
    const float* eta = (const float*)d_in[8];
    const float* g   = (const float*)d_in[9];
    const float* b   = (const float*)d_in[10];

    k_gemm_s<<<256, 256>>>(x, Wi);
    k_gemm_z<<<256, 256>>>(Wz);
    k_gemm_zc<<<256, 256>>>(Wc);
    memnet_rec_kernel<<<NBLK, NTH>>>(Wh, Who, Wo, lam, eta, g, b, (float*)d_out);
}